// round 1
// baseline (speedup 1.0000x reference)
#include <cuda_runtime.h>
#include <math.h>

// ---------------- problem constants ----------------
#define L_TOK   4096
#define DMODEL  3584
#define NH      112
#define HD      64
#define DS      64
#define CHUNKSZ 256
#define NCHUNK  16
#define NG      2
#define HPG     (NH / NG)          // 56
#define INNER   (NH * HD)          // 7168
#define IN2     (2 * INNER)        // 14336

// ---------------- scratch (device globals; no cudaMalloc allowed) ----------
__device__ float g_xz[(size_t)L_TOK * IN2];            // 235 MB: [x | z]
__device__ float g_yg[(size_t)L_TOK * INNER];          // 117 MB: gated y
__device__ float g_states[(size_t)NCHUNK * NH * HD * DS];   // [k][h][p][n]
__device__ float g_prev[(size_t)NCHUNK * NH * DS * HD];     // [k][h][n][p] (transposed)
__device__ float g_dt[NH];
__device__ float g_a[NH];

// ---------------- packed f32x2 FMA (doubles fp32 throughput on sm_10x) -----
__device__ __forceinline__ void ffma2(float2 &d, const float2 &a, const float2 &b) {
    unsigned long long ud, ua, ub;
    __builtin_memcpy(&ud, &d, 8);
    __builtin_memcpy(&ua, &a, 8);
    __builtin_memcpy(&ub, &b, 8);
    asm("fma.rn.f32x2 %0, %1, %2, %0;" : "+l"(ud) : "l"(ua), "l"(ub));
    __builtin_memcpy(&d, &ud, 8);
}

// ---------------- per-head parameters --------------------------------------
__global__ void hparams_kernel(const float* __restrict__ A_log,
                               const float* __restrict__ dt_bias) {
    int h = threadIdx.x;
    if (h < NH) {
        float xv = 0.1f + dt_bias[h];
        float sp = (xv > 20.f) ? xv : log1pf(expf(xv));   // softplus
        g_dt[h] = sp;
        g_a[h]  = -expf(A_log[h]) * sp;                   // dt * A (negative)
    }
}

// ---------------- SGEMM: C[M,N] = A[M,K] * B[N,K]^T (all row-major) --------
#define LDT 132
__global__ __launch_bounds__(256)
void sgemm_nt(const float* __restrict__ A, const float* __restrict__ B,
              float* __restrict__ C, int M, int N, int K) {
    __shared__ __align__(16) float As[16 * LDT];
    __shared__ __align__(16) float Bs[16 * LDT];
    int tid = threadIdx.x;
    int tx = tid & 15, ty = tid >> 4;
    int n0 = blockIdx.x * 128, m0 = blockIdx.y * 128;

    float2 acc[8][4];
    #pragma unroll
    for (int i = 0; i < 8; i++)
        #pragma unroll
        for (int j = 0; j < 4; j++) acc[i][j] = make_float2(0.f, 0.f);

    for (int kb = 0; kb < K; kb += 16) {
        #pragma unroll
        for (int it = 0; it < 2; it++) {
            int q = tid + it * 256;           // 512 float4 loads per tile
            int r = q >> 2, c4 = (q & 3) * 4;
            float4 va = *(const float4*)&A[(size_t)(m0 + r) * K + kb + c4];
            As[(c4 + 0) * LDT + r] = va.x;
            As[(c4 + 1) * LDT + r] = va.y;
            As[(c4 + 2) * LDT + r] = va.z;
            As[(c4 + 3) * LDT + r] = va.w;
            float4 vb = *(const float4*)&B[(size_t)(n0 + r) * K + kb + c4];
            Bs[(c4 + 0) * LDT + r] = vb.x;
            Bs[(c4 + 1) * LDT + r] = vb.y;
            Bs[(c4 + 2) * LDT + r] = vb.z;
            Bs[(c4 + 3) * LDT + r] = vb.w;
        }
        __syncthreads();
        #pragma unroll
        for (int k = 0; k < 16; k++) {
            const float* Ar = &As[k * LDT + ty * 8];
            float4 a0 = *(const float4*)Ar;
            float4 a1 = *(const float4*)(Ar + 4);
            const float* Br = &Bs[k * LDT + tx * 8];
            float4 b0 = *(const float4*)Br;
            float4 b1 = *(const float4*)(Br + 4);
            float av[8] = {a0.x, a0.y, a0.z, a0.w, a1.x, a1.y, a1.z, a1.w};
            float2 bb[4] = {make_float2(b0.x, b0.y), make_float2(b0.z, b0.w),
                            make_float2(b1.x, b1.y), make_float2(b1.z, b1.w)};
            #pragma unroll
            for (int i = 0; i < 8; i++) {
                float2 aa = make_float2(av[i], av[i]);
                #pragma unroll
                for (int j = 0; j < 4; j++) ffma2(acc[i][j], aa, bb[j]);
            }
        }
        __syncthreads();
    }
    #pragma unroll
    for (int i = 0; i < 8; i++) {
        float* Cr = &C[(size_t)(m0 + ty * 8 + i) * N + n0 + tx * 8];
        *(float4*)Cr       = make_float4(acc[i][0].x, acc[i][0].y, acc[i][1].x, acc[i][1].y);
        *(float4*)(Cr + 4) = make_float4(acc[i][2].x, acc[i][2].y, acc[i][3].x, acc[i][3].y);
    }
}

// ---------------- per-chunk end states: S[k,h,p,n] --------------------------
// S = sum_j exp((C-1-j)*a) * dt * x[j,p] * B[j,n]
__global__ void states_kernel(const float* __restrict__ Bin) {
    int k = blockIdx.x, h = blockIdx.y;
    int tid = threadIdx.x;
    int p = tid & 63, quad = tid >> 6;     // thread -> (p, n = quad + 4m)
    float a = g_a[h], dtv = g_dt[h];
    int g = h / HPG;
    __shared__ float sx[8 * 64], sb[8 * 64];
    float acc[16];
    #pragma unroll
    for (int m = 0; m < 16; m++) acc[m] = 0.f;
    int lb = k * CHUNKSZ;
    for (int jb = 0; jb < CHUNKSZ; jb += 8) {
        __syncthreads();
        #pragma unroll
        for (int it = 0; it < 2; it++) {
            int e = tid + it * 256;
            int jj = e >> 6, pp = e & 63;
            int l = lb + jb + jj;
            sx[e] = g_xz[(size_t)l * IN2 + h * HD + pp];
            sb[e] = Bin[((size_t)l * NG + g) * DS + pp];
        }
        __syncthreads();
        #pragma unroll
        for (int jj = 0; jj < 8; jj++) {
            int j = jb + jj;
            float dec = expf(a * (float)(CHUNKSZ - 1 - j)) * dtv;
            float v = sx[jj * 64 + p] * dec;
            #pragma unroll
            for (int m = 0; m < 16; m++)
                acc[m] += v * sb[jj * 64 + quad + 4 * m];
        }
    }
    size_t base = ((size_t)(k * NH + h)) << 12;   // 64*64 per (k,h)
    #pragma unroll
    for (int m = 0; m < 16; m++)
        g_states[base + p * 64 + quad + 4 * m] = acc[m];
}

// ---------------- inter-chunk scan (16 sequential steps) --------------------
// prev[k] = state ENTERING chunk k; stored transposed [n][p] for Y_off reads.
__global__ void scan_kernel() {
    int h = blockIdx.x;
    float cd = expf(g_a[h] * (float)CHUNKSZ);
    for (int e = threadIdx.x; e < HD * DS; e += 256) {
        int p = e >> 6, n = e & 63;
        float carry = 0.f;
        #pragma unroll
        for (int k = 0; k < NCHUNK; k++) {
            size_t base = ((size_t)(k * NH + h)) << 12;
            g_prev[base + n * 64 + p] = carry;
            carry = carry * cd + g_states[base + e];
        }
    }
}

// ---------------- intra-chunk + off-diagonal + gate -------------------------
// One block per (chunk k, head h); thread i owns output row i of the chunk.
#define CLD 65
#define SY_FLOATS (256*64 + 256*64 + 64*64 + 256*CLD + 288)
__global__ __launch_bounds__(256, 1)
void yblock_kernel(const float* __restrict__ Bin, const float* __restrict__ Cin,
                   const float* __restrict__ Dv) {
    extern __shared__ float sm[];
    float* sX   = sm;                    // [256][64] raw x
    float* sB   = sX + 256 * 64;         // [256][64]
    float* sP   = sB + 256 * 64;         // [64][64] prev transposed [n][p]
    float* sC   = sP + 64 * 64;          // [256][CLD] (conflict-free pad)
    float* sDec = sC + 256 * CLD;        // exp(d*a), d = 0..256

    int k = blockIdx.x, h = blockIdx.y;
    int tid = threadIdx.x;
    float a = g_a[h], dtv = g_dt[h], Dh = Dv[h];
    int g = h / HPG;
    int lb = k * CHUNKSZ;

    float4* sX4 = (float4*)sX;
    float4* sB4 = (float4*)sB;
    float4* sP4 = (float4*)sP;
    #pragma unroll
    for (int it = 0; it < 16; it++) {
        int q = tid + it * 256;          // float4 index over [256][16]
        int j = q >> 4, p4 = q & 15;
        sX4[q] = *(const float4*)&g_xz[(size_t)(lb + j) * IN2 + h * HD + p4 * 4];
        sB4[q] = *(const float4*)&Bin[((size_t)(lb + j) * NG + g) * DS + p4 * 4];
    }
    {
        size_t pbase = ((size_t)(k * NH + h)) << 12;
        #pragma unroll
        for (int it = 0; it < 4; it++) {
            int q = tid + it * 256;
            sP4[q] = *(const float4*)&g_prev[pbase + (size_t)q * 4];
        }
    }
    for (int d = tid; d < CHUNKSZ + 1; d += 256) sDec[d] = expf(a * (float)d);

    // this thread's C row -> registers (for diag dot) + smem (for off-diag)
    float cre[64];
    {
        const float4* Crow = (const float4*)&Cin[((size_t)(lb + tid) * NG + g) * DS];
        #pragma unroll
        for (int n4 = 0; n4 < 16; n4++) {
            float4 v = Crow[n4];
            cre[4 * n4 + 0] = v.x; cre[4 * n4 + 1] = v.y;
            cre[4 * n4 + 2] = v.z; cre[4 * n4 + 3] = v.w;
            sC[tid * CLD + 4 * n4 + 0] = v.x;
            sC[tid * CLD + 4 * n4 + 1] = v.y;
            sC[tid * CLD + 4 * n4 + 2] = v.z;
            sC[tid * CLD + 4 * n4 + 3] = v.w;
        }
    }
    __syncthreads();

    int i = tid;
    float acc[64];
    #pragma unroll
    for (int p = 0; p < 64; p++) acc[p] = 0.f;

    // 1) intra-chunk: sum_{j<=i} (C_i . B_j) * exp((i-j)a) * dt * x_j
    for (int j = 0; j <= i; j++) {
        const float4* bj = (const float4*)&sB[j * 64];
        float s = 0.f;
        #pragma unroll
        for (int m4 = 0; m4 < 16; m4++) {
            float4 bv = bj[m4];
            s += cre[4 * m4 + 0] * bv.x + cre[4 * m4 + 1] * bv.y
               + cre[4 * m4 + 2] * bv.z + cre[4 * m4 + 3] * bv.w;
        }
        float w = s * sDec[i - j] * dtv;
        const float4* xj = (const float4*)&sX[j * 64];
        #pragma unroll
        for (int p4 = 0; p4 < 16; p4++) {
            float4 xv = xj[p4];
            acc[4 * p4 + 0] += w * xv.x; acc[4 * p4 + 1] += w * xv.y;
            acc[4 * p4 + 2] += w * xv.z; acc[4 * p4 + 3] += w * xv.w;
        }
    }

    // 2) off-diagonal: exp((i+1)a) * sum_n C_i[n] * prev[p][n]
    {
        float coef = sDec[i + 1];
        for (int n = 0; n < 64; n++) {
            float w = sC[i * CLD + n] * coef;
            const float4* pn = (const float4*)&sP[n * 64];
            #pragma unroll
            for (int p4 = 0; p4 < 16; p4++) {
                float4 pv = pn[p4];
                acc[4 * p4 + 0] += w * pv.x; acc[4 * p4 + 1] += w * pv.y;
                acc[4 * p4 + 2] += w * pv.z; acc[4 * p4 + 3] += w * pv.w;
            }
        }
    }

    // 3) + x*D, gate with sigmoid(z), store
    {
        int l = lb + i;
        const float* zrow = &g_xz[(size_t)l * IN2 + INNER + h * HD];
        const float* xrow = &sX[i * 64];
        float* outp = &g_yg[(size_t)l * INNER + h * HD];
        #pragma unroll
        for (int p4 = 0; p4 < 16; p4++) {
            float4 zv = *(const float4*)&zrow[p4 * 4];
            float4 xv = *(const float4*)&xrow[p4 * 4];
            float4 o;
            o.x = (acc[4 * p4 + 0] + xv.x * Dh) / (1.f + expf(-zv.x));
            o.y = (acc[4 * p4 + 1] + xv.y * Dh) / (1.f + expf(-zv.y));
            o.z = (acc[4 * p4 + 2] + xv.z * Dh) / (1.f + expf(-zv.z));
            o.w = (acc[4 * p4 + 3] + xv.w * Dh) / (1.f + expf(-zv.w));
            *(float4*)&outp[p4 * 4] = o;
        }
    }
}

// ---------------- launcher --------------------------------------------------
extern "C" void kernel_launch(void* const* d_in, const int* in_sizes, int n_in,
                              void* d_out, int out_size) {
    (void)in_sizes; (void)n_in; (void)out_size;
    const float* hidden = (const float*)d_in[0];
    const float* W_in   = (const float*)d_in[1];
    const float* W_out  = (const float*)d_in[2];
    const float* A_log  = (const float*)d_in[3];
    const float* Dv     = (const float*)d_in[4];
    const float* dtb    = (const float*)d_in[5];
    const float* Bin    = (const float*)d_in[6];
    const float* Cin    = (const float*)d_in[7];
    float* out = (float*)d_out;

    float *xz_ptr = nullptr, *yg_ptr = nullptr;
    cudaGetSymbolAddress((void**)&xz_ptr, g_xz);
    cudaGetSymbolAddress((void**)&yg_ptr, g_yg);

    hparams_kernel<<<1, 128>>>(A_log, dtb);

    // GEMM1: xz[L, 2*inner] = hidden[L, DMODEL] @ W_in[2*inner, DMODEL]^T
    {
        dim3 grid(IN2 / 128, L_TOK / 128);   // 112 x 32
        sgemm_nt<<<grid, 256>>>(hidden, W_in, xz_ptr, L_TOK, IN2, DMODEL);
    }

    states_kernel<<<dim3(NCHUNK, NH), 256>>>(Bin);
    scan_kernel<<<NH, 256>>>();

    {
        size_t smem = (size_t)SY_FLOATS * sizeof(float);   // ~215 KB
        cudaFuncSetAttribute(yblock_kernel,
                             cudaFuncAttributeMaxDynamicSharedMemorySize, (int)smem);
        yblock_kernel<<<dim3(NCHUNK, NH), 256, smem>>>(Bin, Cin, Dv);
    }

    // GEMM2: out[L, DMODEL] = yg[L, inner] @ W_out[DMODEL, inner]^T
    {
        dim3 grid(DMODEL / 128, L_TOK / 128);   // 28 x 32
        sgemm_nt<<<grid, 256>>>(yg_ptr, W_out, out, L_TOK, DMODEL, INNER);
    }
}

// round 3
// speedup vs baseline: 2.8496x; 2.8496x over previous
#include <cuda_runtime.h>
#include <math.h>
#include <stdint.h>

// ---------------- problem constants ----------------
#define L_TOK   4096
#define DMODEL  3584
#define NH      112
#define HD      64
#define DS      64
#define CHUNKSZ 256
#define NCHUNK  16
#define NG      2
#define HPG     (NH / NG)          // 56
#define INNER   (NH * HD)          // 7168
#define IN2     (2 * INNER)        // 14336

// ---------------- scratch (device globals; no cudaMalloc allowed) ----------
__device__ float g_xz[(size_t)L_TOK * IN2];            // [x | z]
__device__ float g_yg[(size_t)L_TOK * INNER];          // gated y
__device__ float g_states[(size_t)NCHUNK * NH * HD * DS];   // [k][h][p][n]
__device__ float g_prev[(size_t)NCHUNK * NH * DS * HD];     // [k][h][n][p]
__device__ float g_hid[(size_t)L_TOK * DMODEL];        // tf32-rounded hidden
__device__ float g_w1[(size_t)IN2 * DMODEL];           // tf32-rounded W_in
__device__ float g_w2[(size_t)DMODEL * INNER];         // tf32-rounded W_out
__device__ float g_dt[NH];
__device__ float g_a[NH];

// ---------------- helpers ---------------------------------------------------
__device__ __forceinline__ uint32_t s2u(const void* p) {
    uint32_t a;
    asm("{ .reg .u64 t; cvta.to.shared.u64 t, %1; cvt.u32.u64 %0, t; }"
        : "=r"(a) : "l"(p));
    return a;
}
__device__ __forceinline__ void cpasync16(uint32_t saddr, const void* g) {
    asm volatile("cp.async.cg.shared.global [%0], [%1], 16;" :: "r"(saddr), "l"(g));
}
__device__ __forceinline__ float rtf32(float x) {
    uint32_t r;
    asm("cvt.rna.tf32.f32 %0, %1;" : "=r"(r) : "f"(x));
    return __uint_as_float(r);
}
// m16n8k8 tf32 mma (sm_80 baseline PTX — no 'a' arch feature needed)
__device__ __forceinline__ void mma16n8k8(float* d, const float* a, float b0, float b1) {
    asm volatile(
        "mma.sync.aligned.m16n8k8.row.col.f32.tf32.tf32.f32 "
        "{%0,%1,%2,%3}, {%4,%5,%6,%7}, {%8,%9}, {%0,%1,%2,%3};"
        : "+f"(d[0]), "+f"(d[1]), "+f"(d[2]), "+f"(d[3])
        : "r"(__float_as_uint(a[0])), "r"(__float_as_uint(a[1])),
          "r"(__float_as_uint(a[2])), "r"(__float_as_uint(a[3])),
          "r"(__float_as_uint(b0)), "r"(__float_as_uint(b1)));
}

// ---------------- per-head parameters --------------------------------------
__global__ void hparams_kernel(const float* __restrict__ A_log,
                               const float* __restrict__ dt_bias) {
    int h = threadIdx.x;
    if (h < NH) {
        float xv = 0.1f + dt_bias[h];
        float sp = (xv > 20.f) ? xv : log1pf(expf(xv));
        g_dt[h] = sp;
        g_a[h]  = -expf(A_log[h]) * sp;
    }
}

// ---------------- round-to-nearest tf32 preprocessing ----------------------
__global__ void round_tf32_kernel(const float* __restrict__ in, float* __restrict__ out, int n4) {
    int i = blockIdx.x * blockDim.x + threadIdx.x;
    int stride = gridDim.x * blockDim.x;
    for (; i < n4; i += stride) {
        float4 v = ((const float4*)in)[i];
        v.x = rtf32(v.x); v.y = rtf32(v.y); v.z = rtf32(v.z); v.w = rtf32(v.w);
        ((float4*)out)[i] = v;
    }
}

// ---------------- mma.sync TF32 GEMM: C[M,N] = A[M,K]*B[N,K]^T -------------
// Block tile 128(M) x 256(N) x 32(K); 8 warps as 2(m) x 4(n); warp tile 64x64.
// Smem rows stride 36 floats -> conflict-free fragment loads.
#define KT       32
#define ALD      36
#define A_FLT    (128 * ALD)                 // 4608 floats / stage
#define B_FLT    (256 * ALD)                 // 9216 floats / stage
#define STG_FLT  (A_FLT + B_FLT)             // 13824
#define NSTG     3
#define GM_SMEM  (NSTG * STG_FLT * 4)        // 165888 B

__global__ __launch_bounds__(256, 1)
void gemm_mma(const float* __restrict__ A, const float* __restrict__ B,
              float* __restrict__ C, int M, int N, int K, int tiles_m) {
    extern __shared__ __align__(16) float sm[];
    uint32_t sbase = s2u(sm);

    int tid = threadIdx.x, lane = tid & 31, wid = tid >> 5;
    int wm = (wid & 1) * 64;          // warp m offset in block tile
    int wn = (wid >> 1) * 64;         // warp n offset
    int bid = blockIdx.x;
    int m0 = (bid % tiles_m) * 128;
    int n0 = (bid / tiles_m) * 256;

    // per-thread cp.async source pointers + smem byte offsets
    const float* gA[4]; uint32_t oA[4];
    #pragma unroll
    for (int it = 0; it < 4; it++) {
        int q = tid + it * 256;             // 1024 float4 over A tile
        int r = q >> 3, c4 = (q & 7) * 4;
        gA[it] = A + (size_t)(m0 + r) * K + c4;
        oA[it] = (uint32_t)(r * ALD + c4) * 4;
    }
    const float* gB[8]; uint32_t oB[8];
    #pragma unroll
    for (int it = 0; it < 8; it++) {
        int q = tid + it * 256;             // 2048 float4 over B tile
        int r = q >> 3, c4 = (q & 7) * 4;
        gB[it] = B + (size_t)(n0 + r) * K + c4;
        oB[it] = (uint32_t)(A_FLT + r * ALD + c4) * 4;
    }

    const int NKC = K / KT;

    // prologue: fill all 3 stages
    #pragma unroll
    for (int s = 0; s < NSTG; s++) {
        uint32_t sb = sbase + s * (STG_FLT * 4);
        #pragma unroll
        for (int it = 0; it < 4; it++) cpasync16(sb + oA[it], gA[it] + s * KT);
        #pragma unroll
        for (int it = 0; it < 8; it++) cpasync16(sb + oB[it], gB[it] + s * KT);
        asm volatile("cp.async.commit_group;");
    }

    float acc[4][8][4];
    #pragma unroll
    for (int t = 0; t < 4; t++)
        #pragma unroll
        for (int u = 0; u < 8; u++)
            #pragma unroll
            for (int v = 0; v < 4; v++) acc[t][u][v] = 0.f;

    int g4 = lane >> 2, c4i = lane & 3;

    for (int kb = 0; kb < NKC; kb++) {
        int st = kb % NSTG;
        asm volatile("cp.async.wait_group %0;" :: "n"(NSTG - 1));
        __syncthreads();

        const float* As = sm + st * STG_FLT;
        const float* Bs = As + A_FLT;

        #pragma unroll
        for (int ks = 0; ks < 4; ks++) {
            int kc = ks * 8 + c4i;
            float a[4][4];
            #pragma unroll
            for (int t = 0; t < 4; t++) {
                int r = wm + t * 16 + g4;
                a[t][0] = As[r * ALD + kc];
                a[t][1] = As[(r + 8) * ALD + kc];
                a[t][2] = As[r * ALD + kc + 4];
                a[t][3] = As[(r + 8) * ALD + kc + 4];
            }
            #pragma unroll
            for (int u = 0; u < 8; u++) {
                int n = wn + u * 8 + g4;
                float b0 = Bs[n * ALD + kc];
                float b1 = Bs[n * ALD + kc + 4];
                #pragma unroll
                for (int t = 0; t < 4; t++) mma16n8k8(acc[t][u], a[t], b0, b1);
            }
        }
        __syncthreads();

        if (kb + NSTG < NKC) {
            uint32_t sb = sbase + st * (STG_FLT * 4);
            #pragma unroll
            for (int it = 0; it < 4; it++) cpasync16(sb + oA[it], gA[it] + (kb + NSTG) * KT);
            #pragma unroll
            for (int it = 0; it < 8; it++) cpasync16(sb + oB[it], gB[it] + (kb + NSTG) * KT);
        }
        asm volatile("cp.async.commit_group;");
    }

    // epilogue: direct global stores (float2 per fragment half)
    #pragma unroll
    for (int t = 0; t < 4; t++) {
        int r0 = m0 + wm + t * 16 + g4;
        #pragma unroll
        for (int u = 0; u < 8; u++) {
            int col = n0 + wn + u * 8 + c4i * 2;
            *(float2*)&C[(size_t)r0 * N + col] = make_float2(acc[t][u][0], acc[t][u][1]);
            *(float2*)&C[(size_t)(r0 + 8) * N + col] = make_float2(acc[t][u][2], acc[t][u][3]);
        }
    }
}

// ---------------- per-chunk end states: S[k,h,p,n] --------------------------
__global__ void states_kernel(const float* __restrict__ Bin) {
    int k = blockIdx.x, h = blockIdx.y;
    int tid = threadIdx.x;
    int p = tid & 63, quad = tid >> 6;
    float a = g_a[h], dtv = g_dt[h];
    int g = h / HPG;
    __shared__ float sx[8 * 64], sbuf[8 * 64];
    float acc[16];
    #pragma unroll
    for (int m = 0; m < 16; m++) acc[m] = 0.f;
    int lb = k * CHUNKSZ;
    for (int jb = 0; jb < CHUNKSZ; jb += 8) {
        __syncthreads();
        #pragma unroll
        for (int it = 0; it < 2; it++) {
            int e = tid + it * 256;
            int jj = e >> 6, pp = e & 63;
            int l = lb + jb + jj;
            sx[e] = g_xz[(size_t)l * IN2 + h * HD + pp];
            sbuf[e] = Bin[((size_t)l * NG + g) * DS + pp];
        }
        __syncthreads();
        #pragma unroll
        for (int jj = 0; jj < 8; jj++) {
            int j = jb + jj;
            float dec = expf(a * (float)(CHUNKSZ - 1 - j)) * dtv;
            float v = sx[jj * 64 + p] * dec;
            #pragma unroll
            for (int m = 0; m < 16; m++)
                acc[m] += v * sbuf[jj * 64 + quad + 4 * m];
        }
    }
    size_t base = ((size_t)(k * NH + h)) << 12;
    #pragma unroll
    for (int m = 0; m < 16; m++)
        g_states[base + p * 64 + quad + 4 * m] = acc[m];
}

// ---------------- inter-chunk scan -----------------------------------------
__global__ void scan_kernel() {
    int h = blockIdx.x;
    float cd = expf(g_a[h] * (float)CHUNKSZ);
    for (int e = threadIdx.x; e < HD * DS; e += 256) {
        int p = e >> 6, n = e & 63;
        float carry = 0.f;
        #pragma unroll
        for (int k = 0; k < NCHUNK; k++) {
            size_t base = ((size_t)(k * NH + h)) << 12;
            g_prev[base + n * 64 + p] = carry;
            carry = carry * cd + g_states[base + e];
        }
    }
}

// ---------------- intra-chunk + off-diagonal + gate -------------------------
#define CLD 65
#define SY_FLOATS (256*64 + 256*64 + 64*64 + 256*CLD + 288)
__global__ __launch_bounds__(256, 1)
void yblock_kernel(const float* __restrict__ Bin, const float* __restrict__ Cin,
                   const float* __restrict__ Dv) {
    extern __shared__ float sm[];
    float* sX   = sm;
    float* sB   = sX + 256 * 64;
    float* sP   = sB + 256 * 64;
    float* sC   = sP + 64 * 64;
    float* sDec = sC + 256 * CLD;

    int k = blockIdx.x, h = blockIdx.y;
    int tid = threadIdx.x;
    float a = g_a[h], dtv = g_dt[h], Dh = Dv[h];
    int g = h / HPG;
    int lb = k * CHUNKSZ;

    float4* sX4 = (float4*)sX;
    float4* sB4 = (float4*)sB;
    float4* sP4 = (float4*)sP;
    #pragma unroll
    for (int it = 0; it < 16; it++) {
        int q = tid + it * 256;
        int j = q >> 4, p4 = q & 15;
        sX4[q] = *(const float4*)&g_xz[(size_t)(lb + j) * IN2 + h * HD + p4 * 4];
        sB4[q] = *(const float4*)&Bin[((size_t)(lb + j) * NG + g) * DS + p4 * 4];
    }
    {
        size_t pbase = ((size_t)(k * NH + h)) << 12;
        #pragma unroll
        for (int it = 0; it < 4; it++) {
            int q = tid + it * 256;
            sP4[q] = *(const float4*)&g_prev[pbase + (size_t)q * 4];
        }
    }
    for (int d = tid; d < CHUNKSZ + 1; d += 256) sDec[d] = expf(a * (float)d);

    float cre[64];
    {
        const float4* Crow = (const float4*)&Cin[((size_t)(lb + tid) * NG + g) * DS];
        #pragma unroll
        for (int n4 = 0; n4 < 16; n4++) {
            float4 v = Crow[n4];
            cre[4 * n4 + 0] = v.x; cre[4 * n4 + 1] = v.y;
            cre[4 * n4 + 2] = v.z; cre[4 * n4 + 3] = v.w;
            sC[tid * CLD + 4 * n4 + 0] = v.x;
            sC[tid * CLD + 4 * n4 + 1] = v.y;
            sC[tid * CLD + 4 * n4 + 2] = v.z;
            sC[tid * CLD + 4 * n4 + 3] = v.w;
        }
    }
    __syncthreads();

    int i = tid;
    float acc[64];
    #pragma unroll
    for (int p = 0; p < 64; p++) acc[p] = 0.f;

    for (int j = 0; j <= i; j++) {
        const float4* bj = (const float4*)&sB[j * 64];
        float s = 0.f;
        #pragma unroll
        for (int m4 = 0; m4 < 16; m4++) {
            float4 bv = bj[m4];
            s += cre[4 * m4 + 0] * bv.x + cre[4 * m4 + 1] * bv.y
               + cre[4 * m4 + 2] * bv.z + cre[4 * m4 + 3] * bv.w;
        }
        float w = s * sDec[i - j] * dtv;
        const float4* xj = (const float4*)&sX[j * 64];
        #pragma unroll
        for (int p4 = 0; p4 < 16; p4++) {
            float4 xv = xj[p4];
            acc[4 * p4 + 0] += w * xv.x; acc[4 * p4 + 1] += w * xv.y;
            acc[4 * p4 + 2] += w * xv.z; acc[4 * p4 + 3] += w * xv.w;
        }
    }
    {
        float coef = sDec[i + 1];
        for (int n = 0; n < 64; n++) {
            float w = sC[i * CLD + n] * coef;
            const float4* pn = (const float4*)&sP[n * 64];
            #pragma unroll
            for (int p4 = 0; p4 < 16; p4++) {
                float4 pv = pn[p4];
                acc[4 * p4 + 0] += w * pv.x; acc[4 * p4 + 1] += w * pv.y;
                acc[4 * p4 + 2] += w * pv.z; acc[4 * p4 + 3] += w * pv.w;
            }
        }
    }
    {
        int l = lb + i;
        const float* zrow = &g_xz[(size_t)l * IN2 + INNER + h * HD];
        const float* xrow = &sX[i * 64];
        float* outp = &g_yg[(size_t)l * INNER + h * HD];
        #pragma unroll
        for (int p4 = 0; p4 < 16; p4++) {
            float4 zv = *(const float4*)&zrow[p4 * 4];
            float4 xv = *(const float4*)&xrow[p4 * 4];
            float4 o;
            o.x = (acc[4 * p4 + 0] + xv.x * Dh) / (1.f + expf(-zv.x));
            o.y = (acc[4 * p4 + 1] + xv.y * Dh) / (1.f + expf(-zv.y));
            o.z = (acc[4 * p4 + 2] + xv.z * Dh) / (1.f + expf(-zv.z));
            o.w = (acc[4 * p4 + 3] + xv.w * Dh) / (1.f + expf(-zv.w));
            *(float4*)&outp[p4 * 4] = o;
        }
    }
}

// ---------------- launcher --------------------------------------------------
extern "C" void kernel_launch(void* const* d_in, const int* in_sizes, int n_in,
                              void* d_out, int out_size) {
    (void)in_sizes; (void)n_in; (void)out_size;
    const float* hidden = (const float*)d_in[0];
    const float* W_in   = (const float*)d_in[1];
    const float* W_out  = (const float*)d_in[2];
    const float* A_log  = (const float*)d_in[3];
    const float* Dv     = (const float*)d_in[4];
    const float* dtb    = (const float*)d_in[5];
    const float* Bin    = (const float*)d_in[6];
    const float* Cin    = (const float*)d_in[7];
    float* out = (float*)d_out;

    float *xz_ptr, *yg_ptr, *hid_ptr, *w1_ptr, *w2_ptr;
    cudaGetSymbolAddress((void**)&xz_ptr, g_xz);
    cudaGetSymbolAddress((void**)&yg_ptr, g_yg);
    cudaGetSymbolAddress((void**)&hid_ptr, g_hid);
    cudaGetSymbolAddress((void**)&w1_ptr, g_w1);
    cudaGetSymbolAddress((void**)&w2_ptr, g_w2);

    hparams_kernel<<<1, 128>>>(A_log, dtb);

    // round GEMM inputs to tf32 (RNA, unbiased) so in-mma truncation is exact
    round_tf32_kernel<<<1184, 256>>>(hidden, hid_ptr, (L_TOK * DMODEL) / 4);
    round_tf32_kernel<<<1184, 256>>>(W_in,   w1_ptr,  (IN2 * DMODEL) / 4);
    round_tf32_kernel<<<1184, 256>>>(W_out,  w2_ptr,  (DMODEL * INNER) / 4);

    cudaFuncSetAttribute(gemm_mma, cudaFuncAttributeMaxDynamicSharedMemorySize, GM_SMEM);

    // GEMM1: xz[L, IN2] = hid[L, DMODEL] @ W_in[IN2, DMODEL]^T
    {
        int tiles_m = L_TOK / 128;      // 32
        int tiles_n = IN2 / 256;        // 56
        gemm_mma<<<tiles_m * tiles_n, 256, GM_SMEM>>>(hid_ptr, w1_ptr, xz_ptr,
                                                      L_TOK, IN2, DMODEL, tiles_m);
    }

    states_kernel<<<dim3(NCHUNK, NH), 256>>>(Bin);
    scan_kernel<<<NH, 256>>>();

    {
        size_t smem = (size_t)SY_FLOATS * sizeof(float);
        cudaFuncSetAttribute(yblock_kernel,
                             cudaFuncAttributeMaxDynamicSharedMemorySize, (int)smem);
        yblock_kernel<<<dim3(NCHUNK, NH), 256, smem>>>(Bin, Cin, Dv);
    }

    // round yg in place, then GEMM2
    round_tf32_kernel<<<1184, 256>>>(yg_ptr, yg_ptr, (L_TOK * INNER) / 4);

    // GEMM2: out[L, DMODEL] = yg[L, INNER] @ W_out[DMODEL, INNER]^T
    {
        int tiles_m = L_TOK / 128;      // 32
        int tiles_n = DMODEL / 256;     // 14
        gemm_mma<<<tiles_m * tiles_n, 256, GM_SMEM>>>(yg_ptr, w2_ptr, out,
                                                      L_TOK, DMODEL, INNER, tiles_m);
    }
}

// round 4
// speedup vs baseline: 2.9268x; 1.0271x over previous
#include <cuda_runtime.h>
#include <math.h>
#include <stdint.h>

// ---------------- problem constants ----------------
#define L_TOK   4096
#define DMODEL  3584
#define NH      112
#define HD      64
#define DS      64
#define CHUNKSZ 256
#define NCHUNK  16
#define NG      2
#define HPG     (NH / NG)          // 56
#define INNER   (NH * HD)          // 7168
#define IN2     (2 * INNER)        // 14336

// ---------------- scratch (device globals; no cudaMalloc allowed) ----------
__device__ float g_xz[(size_t)L_TOK * IN2];            // [x | z]
__device__ float g_yg[(size_t)L_TOK * INNER];          // gated y (tf32-rounded)
__device__ float g_states[(size_t)NCHUNK * NH * HD * DS];   // [k][h][p][n]
__device__ float g_prev[(size_t)NCHUNK * NH * DS * HD];     // [k][h][n][p]
__device__ float g_hid[(size_t)L_TOK * DMODEL];        // tf32-rounded hidden
__device__ float g_w1[(size_t)IN2 * DMODEL];           // tf32-rounded W_in
__device__ float g_w2[(size_t)DMODEL * INNER];         // tf32-rounded W_out
__device__ float g_dt[NH];
__device__ float g_a[NH];

// ---------------- helpers ---------------------------------------------------
__device__ __forceinline__ uint32_t s2u(const void* p) {
    uint32_t a;
    asm("{ .reg .u64 t; cvta.to.shared.u64 t, %1; cvt.u32.u64 %0, t; }"
        : "=r"(a) : "l"(p));
    return a;
}
__device__ __forceinline__ void cpasync16(uint32_t saddr, const void* g) {
    asm volatile("cp.async.cg.shared.global [%0], [%1], 16;" :: "r"(saddr), "l"(g));
}
__device__ __forceinline__ float rtf32(float x) {
    uint32_t r;
    asm("cvt.rna.tf32.f32 %0, %1;" : "=r"(r) : "f"(x));
    return __uint_as_float(r);
}
__device__ __forceinline__ void ffma2(float2 &d, const float2 &a, const float2 &b) {
    unsigned long long ud, ua, ub;
    __builtin_memcpy(&ud, &d, 8);
    __builtin_memcpy(&ua, &a, 8);
    __builtin_memcpy(&ub, &b, 8);
    asm("fma.rn.f32x2 %0, %1, %2, %0;" : "+l"(ud) : "l"(ua), "l"(ub));
    __builtin_memcpy(&d, &ud, 8);
}
// m16n8k8 tf32 mma (sm_80 baseline PTX — no 'a' arch feature needed)
__device__ __forceinline__ void mma16n8k8(float* d, const float* a, float b0, float b1) {
    asm volatile(
        "mma.sync.aligned.m16n8k8.row.col.f32.tf32.tf32.f32 "
        "{%0,%1,%2,%3}, {%4,%5,%6,%7}, {%8,%9}, {%0,%1,%2,%3};"
        : "+f"(d[0]), "+f"(d[1]), "+f"(d[2]), "+f"(d[3])
        : "r"(__float_as_uint(a[0])), "r"(__float_as_uint(a[1])),
          "r"(__float_as_uint(a[2])), "r"(__float_as_uint(a[3])),
          "r"(__float_as_uint(b0)), "r"(__float_as_uint(b1)));
}

// ---------------- per-head parameters --------------------------------------
__global__ void hparams_kernel(const float* __restrict__ A_log,
                               const float* __restrict__ dt_bias) {
    int h = threadIdx.x;
    if (h < NH) {
        float xv = 0.1f + dt_bias[h];
        float sp = (xv > 20.f) ? xv : log1pf(expf(xv));
        g_dt[h] = sp;
        g_a[h]  = -expf(A_log[h]) * sp;
    }
}

// ---------------- round-to-nearest tf32 preprocessing ----------------------
__global__ void round_tf32_kernel(const float* __restrict__ in, float* __restrict__ out, int n4) {
    int i = blockIdx.x * blockDim.x + threadIdx.x;
    int stride = gridDim.x * blockDim.x;
    for (; i < n4; i += stride) {
        float4 v = ((const float4*)in)[i];
        v.x = rtf32(v.x); v.y = rtf32(v.y); v.z = rtf32(v.z); v.w = rtf32(v.w);
        ((float4*)out)[i] = v;
    }
}

// ---------------- mma.sync TF32 GEMM: C[M,N] = A[M,K]*B[N,K]^T -------------
// Block tile 128(M) x 256(N) x 32(K); 8 warps as 2(m) x 4(n); warp tile 64x64.
// 4-stage cp.async multistage, ONE __syncthreads per k-iteration.
#define KT       32
#define ALD      36
#define A_FLT    (128 * ALD)                 // 4608 floats / stage
#define B_FLT    (256 * ALD)                 // 9216 floats / stage
#define STG_FLT  (A_FLT + B_FLT)             // 13824 floats
#define NSTG     4
#define GM_SMEM  (NSTG * STG_FLT * 4)        // 221184 B

__global__ __launch_bounds__(256, 1)
void gemm_mma(const float* __restrict__ A, const float* __restrict__ B,
              float* __restrict__ C, int M, int N, int K, int tiles_m) {
    extern __shared__ __align__(16) float sm[];
    uint32_t sbase = s2u(sm);

    int tid = threadIdx.x, lane = tid & 31, wid = tid >> 5;
    int wm = (wid & 1) * 64;
    int wn = (wid >> 1) * 64;
    int bid = blockIdx.x;
    int m0 = (bid % tiles_m) * 128;
    int n0 = (bid / tiles_m) * 256;

    const float* gA[4]; uint32_t oA[4];
    #pragma unroll
    for (int it = 0; it < 4; it++) {
        int q = tid + it * 256;
        int r = q >> 3, c4 = (q & 7) * 4;
        gA[it] = A + (size_t)(m0 + r) * K + c4;
        oA[it] = (uint32_t)(r * ALD + c4) * 4;
    }
    const float* gB[8]; uint32_t oB[8];
    #pragma unroll
    for (int it = 0; it < 8; it++) {
        int q = tid + it * 256;
        int r = q >> 3, c4 = (q & 7) * 4;
        gB[it] = B + (size_t)(n0 + r) * K + c4;
        oB[it] = (uint32_t)(A_FLT + r * ALD + c4) * 4;
    }

    const int NKC = K / KT;

    // prologue: fill stages 0..NSTG-2 with chunks 0..NSTG-2
    #pragma unroll
    for (int s = 0; s < NSTG - 1; s++) {
        uint32_t sb = sbase + s * (STG_FLT * 4);
        #pragma unroll
        for (int it = 0; it < 4; it++) cpasync16(sb + oA[it], gA[it] + s * KT);
        #pragma unroll
        for (int it = 0; it < 8; it++) cpasync16(sb + oB[it], gB[it] + s * KT);
        asm volatile("cp.async.commit_group;");
    }

    float acc[4][8][4];
    #pragma unroll
    for (int t = 0; t < 4; t++)
        #pragma unroll
        for (int u = 0; u < 8; u++)
            #pragma unroll
            for (int v = 0; v < 4; v++) acc[t][u][v] = 0.f;

    int g4 = lane >> 2, c4i = lane & 3;

    for (int kb = 0; kb < NKC; kb++) {
        int st = kb & (NSTG - 1);
        asm volatile("cp.async.wait_group %0;" :: "n"(NSTG - 2));
        __syncthreads();

        // refill the stage consumed at iter kb-1 with chunk kb+NSTG-1
        {
            int fc = kb + NSTG - 1;
            if (fc < NKC) {
                int fs = (kb + NSTG - 1) & (NSTG - 1);   // == (kb-1) mod NSTG
                uint32_t sb = sbase + fs * (STG_FLT * 4);
                #pragma unroll
                for (int it = 0; it < 4; it++) cpasync16(sb + oA[it], gA[it] + fc * KT);
                #pragma unroll
                for (int it = 0; it < 8; it++) cpasync16(sb + oB[it], gB[it] + fc * KT);
            }
            asm volatile("cp.async.commit_group;");
        }

        const float* As = sm + st * STG_FLT;
        const float* Bs = As + A_FLT;

        #pragma unroll
        for (int ks = 0; ks < 4; ks++) {
            int kc = ks * 8 + c4i;
            float a[4][4];
            #pragma unroll
            for (int t = 0; t < 4; t++) {
                int r = wm + t * 16 + g4;
                a[t][0] = As[r * ALD + kc];
                a[t][1] = As[(r + 8) * ALD + kc];
                a[t][2] = As[r * ALD + kc + 4];
                a[t][3] = As[(r + 8) * ALD + kc + 4];
            }
            #pragma unroll
            for (int u = 0; u < 8; u++) {
                int n = wn + u * 8 + g4;
                float b0 = Bs[n * ALD + kc];
                float b1 = Bs[n * ALD + kc + 4];
                #pragma unroll
                for (int t = 0; t < 4; t++) mma16n8k8(acc[t][u], a[t], b0, b1);
            }
        }
    }

    #pragma unroll
    for (int t = 0; t < 4; t++) {
        int r0 = m0 + wm + t * 16 + g4;
        #pragma unroll
        for (int u = 0; u < 8; u++) {
            int col = n0 + wn + u * 8 + c4i * 2;
            *(float2*)&C[(size_t)r0 * N + col] = make_float2(acc[t][u][0], acc[t][u][1]);
            *(float2*)&C[(size_t)(r0 + 8) * N + col] = make_float2(acc[t][u][2], acc[t][u][3]);
        }
    }
}

// ---------------- per-chunk end states: S[k,h,p,n] --------------------------
__global__ void states_kernel(const float* __restrict__ Bin) {
    int k = blockIdx.x, h = blockIdx.y;
    int tid = threadIdx.x;
    int p = tid & 63, quad = tid >> 6;
    float a = g_a[h], dtv = g_dt[h];
    int g = h / HPG;
    __shared__ float sx[8 * 64], sbuf[8 * 64];
    float acc[16];
    #pragma unroll
    for (int m = 0; m < 16; m++) acc[m] = 0.f;
    int lb = k * CHUNKSZ;
    for (int jb = 0; jb < CHUNKSZ; jb += 8) {
        __syncthreads();
        #pragma unroll
        for (int it = 0; it < 2; it++) {
            int e = tid + it * 256;
            int jj = e >> 6, pp = e & 63;
            int l = lb + jb + jj;
            sx[e] = g_xz[(size_t)l * IN2 + h * HD + pp];
            sbuf[e] = Bin[((size_t)l * NG + g) * DS + pp];
        }
        __syncthreads();
        #pragma unroll
        for (int jj = 0; jj < 8; jj++) {
            int j = jb + jj;
            float dec = expf(a * (float)(CHUNKSZ - 1 - j)) * dtv;
            float v = sx[jj * 64 + p] * dec;
            #pragma unroll
            for (int m = 0; m < 16; m++)
                acc[m] += v * sbuf[jj * 64 + quad + 4 * m];
        }
    }
    size_t base = ((size_t)(k * NH + h)) << 12;
    #pragma unroll
    for (int m = 0; m < 16; m++)
        g_states[base + p * 64 + quad + 4 * m] = acc[m];
}

// ---------------- inter-chunk scan -----------------------------------------
__global__ void scan_kernel() {
    int h = blockIdx.x;
    float cd = expf(g_a[h] * (float)CHUNKSZ);
    for (int e = threadIdx.x; e < HD * DS; e += 256) {
        int p = e >> 6, n = e & 63;
        float carry = 0.f;
        #pragma unroll
        for (int k = 0; k < NCHUNK; k++) {
            size_t base = ((size_t)(k * NH + h)) << 12;
            g_prev[base + n * 64 + p] = carry;
            carry = carry * cd + g_states[base + e];
        }
    }
}

// ---------------- intra-chunk + off-diagonal + gate (f32x2 packed) ----------
#define CLD 65
#define SY_FLOATS (256*64 + 256*64 + 64*64 + 256*CLD + 288)
__global__ __launch_bounds__(256, 1)
void yblock_kernel(const float* __restrict__ Bin, const float* __restrict__ Cin,
                   const float* __restrict__ Dv) {
    extern __shared__ float sm[];
    float* sX   = sm;
    float* sB   = sX + 256 * 64;
    float* sP   = sB + 256 * 64;
    float* sC   = sP + 64 * 64;
    float* sDec = sC + 256 * CLD;

    int k = blockIdx.x, h = blockIdx.y;
    int tid = threadIdx.x;
    float a = g_a[h], dtv = g_dt[h], Dh = Dv[h];
    int g = h / HPG;
    int lb = k * CHUNKSZ;

    float4* sX4 = (float4*)sX;
    float4* sB4 = (float4*)sB;
    float4* sP4 = (float4*)sP;
    #pragma unroll
    for (int it = 0; it < 16; it++) {
        int q = tid + it * 256;
        int j = q >> 4, p4 = q & 15;
        sX4[q] = *(const float4*)&g_xz[(size_t)(lb + j) * IN2 + h * HD + p4 * 4];
        sB4[q] = *(const float4*)&Bin[((size_t)(lb + j) * NG + g) * DS + p4 * 4];
    }
    {
        size_t pbase = ((size_t)(k * NH + h)) << 12;
        #pragma unroll
        for (int it = 0; it < 4; it++) {
            int q = tid + it * 256;
            sP4[q] = *(const float4*)&g_prev[pbase + (size_t)q * 4];
        }
    }
    for (int d = tid; d < CHUNKSZ + 1; d += 256) sDec[d] = expf(a * (float)d);

    float2 cre2[32];
    {
        const float4* Crow = (const float4*)&Cin[((size_t)(lb + tid) * NG + g) * DS];
        #pragma unroll
        for (int n4 = 0; n4 < 16; n4++) {
            float4 v = Crow[n4];
            cre2[2 * n4 + 0] = make_float2(v.x, v.y);
            cre2[2 * n4 + 1] = make_float2(v.z, v.w);
            sC[tid * CLD + 4 * n4 + 0] = v.x;
            sC[tid * CLD + 4 * n4 + 1] = v.y;
            sC[tid * CLD + 4 * n4 + 2] = v.z;
            sC[tid * CLD + 4 * n4 + 3] = v.w;
        }
    }
    __syncthreads();

    int i = tid;
    float2 acc2[32];
    #pragma unroll
    for (int p = 0; p < 32; p++) acc2[p] = make_float2(0.f, 0.f);

    // 1) intra-chunk (packed f32x2)
    for (int j = 0; j <= i; j++) {
        const float4* bj = (const float4*)&sB[j * 64];
        float2 s2 = make_float2(0.f, 0.f);
        #pragma unroll
        for (int m4 = 0; m4 < 16; m4++) {
            float4 bv = bj[m4];
            ffma2(s2, cre2[2 * m4 + 0], make_float2(bv.x, bv.y));
            ffma2(s2, cre2[2 * m4 + 1], make_float2(bv.z, bv.w));
        }
        float w = (s2.x + s2.y) * sDec[i - j] * dtv;
        float2 w2 = make_float2(w, w);
        const float4* xj = (const float4*)&sX[j * 64];
        #pragma unroll
        for (int p4 = 0; p4 < 16; p4++) {
            float4 xv = xj[p4];
            ffma2(acc2[2 * p4 + 0], w2, make_float2(xv.x, xv.y));
            ffma2(acc2[2 * p4 + 1], w2, make_float2(xv.z, xv.w));
        }
    }

    // 2) off-diagonal
    {
        float coef = sDec[i + 1];
        for (int n = 0; n < 64; n++) {
            float w = sC[i * CLD + n] * coef;
            float2 w2 = make_float2(w, w);
            const float4* pn = (const float4*)&sP[n * 64];
            #pragma unroll
            for (int p4 = 0; p4 < 16; p4++) {
                float4 pv = pn[p4];
                ffma2(acc2[2 * p4 + 0], w2, make_float2(pv.x, pv.y));
                ffma2(acc2[2 * p4 + 1], w2, make_float2(pv.z, pv.w));
            }
        }
    }

    // 3) + x*D, gate with sigmoid(z), round to tf32, store
    {
        int l = lb + i;
        const float* zrow = &g_xz[(size_t)l * IN2 + INNER + h * HD];
        const float* xrow = &sX[i * 64];
        float* outp = &g_yg[(size_t)l * INNER + h * HD];
        #pragma unroll
        for (int p4 = 0; p4 < 16; p4++) {
            float4 zv = *(const float4*)&zrow[p4 * 4];
            float4 xv = *(const float4*)&xrow[p4 * 4];
            float4 o;
            o.x = rtf32((acc2[2 * p4 + 0].x + xv.x * Dh) / (1.f + expf(-zv.x)));
            o.y = rtf32((acc2[2 * p4 + 0].y + xv.y * Dh) / (1.f + expf(-zv.y)));
            o.z = rtf32((acc2[2 * p4 + 1].x + xv.z * Dh) / (1.f + expf(-zv.z)));
            o.w = rtf32((acc2[2 * p4 + 1].y + xv.w * Dh) / (1.f + expf(-zv.w)));
            *(float4*)&outp[p4 * 4] = o;
        }
    }
}

// ---------------- launcher --------------------------------------------------
extern "C" void kernel_launch(void* const* d_in, const int* in_sizes, int n_in,
                              void* d_out, int out_size) {
    (void)in_sizes; (void)n_in; (void)out_size;
    const float* hidden = (const float*)d_in[0];
    const float* W_in   = (const float*)d_in[1];
    const float* W_out  = (const float*)d_in[2];
    const float* A_log  = (const float*)d_in[3];
    const float* Dv     = (const float*)d_in[4];
    const float* dtb    = (const float*)d_in[5];
    const float* Bin    = (const float*)d_in[6];
    const float* Cin    = (const float*)d_in[7];
    float* out = (float*)d_out;

    float *xz_ptr, *yg_ptr, *hid_ptr, *w1_ptr, *w2_ptr;
    cudaGetSymbolAddress((void**)&xz_ptr, g_xz);
    cudaGetSymbolAddress((void**)&yg_ptr, g_yg);
    cudaGetSymbolAddress((void**)&hid_ptr, g_hid);
    cudaGetSymbolAddress((void**)&w1_ptr, g_w1);
    cudaGetSymbolAddress((void**)&w2_ptr, g_w2);

    cudaFuncSetAttribute(gemm_mma, cudaFuncAttributeMaxDynamicSharedMemorySize, GM_SMEM);

    // launch order chosen so gemm1 is the 4th launch (ncu captures it)
    hparams_kernel<<<1, 128>>>(A_log, dtb);                                   // 1
    round_tf32_kernel<<<1184, 256>>>(W_in,   w1_ptr,  (IN2 * DMODEL) / 4);    // 2
    round_tf32_kernel<<<1184, 256>>>(hidden, hid_ptr, (L_TOK * DMODEL) / 4);  // 3

    // GEMM1: xz[L, IN2] = hid[L, DMODEL] @ W_in[IN2, DMODEL]^T
    {
        int tiles_m = L_TOK / 128;      // 32
        int tiles_n = IN2 / 256;        // 56
        gemm_mma<<<tiles_m * tiles_n, 256, GM_SMEM>>>(hid_ptr, w1_ptr, xz_ptr,
                                                      L_TOK, IN2, DMODEL, tiles_m);  // 4
    }

    states_kernel<<<dim3(NCHUNK, NH), 256>>>(Bin);                            // 5
    scan_kernel<<<NH, 256>>>();                                               // 6

    {
        size_t smem = (size_t)SY_FLOATS * sizeof(float);
        cudaFuncSetAttribute(yblock_kernel,
                             cudaFuncAttributeMaxDynamicSharedMemorySize, (int)smem);
        yblock_kernel<<<dim3(NCHUNK, NH), 256, smem>>>(Bin, Cin, Dv);         // 7
    }

    round_tf32_kernel<<<1184, 256>>>(W_out, w2_ptr, (DMODEL * INNER) / 4);    // 8

    // GEMM2: out[L, DMODEL] = yg[L, INNER] @ W_out[DMODEL, INNER]^T
    {
        int tiles_m = L_TOK / 128;      // 32
        int tiles_n = DMODEL / 256;     // 14
        gemm_mma<<<tiles_m * tiles_n, 256, GM_SMEM>>>(yg_ptr, w2_ptr, out,
                                                      L_TOK, DMODEL, INNER, tiles_m); // 9
    }
}

// round 5
// speedup vs baseline: 3.1976x; 1.0925x over previous
#include <cuda_runtime.h>
#include <math.h>
#include <stdint.h>

// ---------------- problem constants ----------------
#define L_TOK   4096
#define DMODEL  3584
#define NH      112
#define HD      64
#define DS      64
#define CHUNKSZ 256
#define NCHUNK  16
#define NG      2
#define HPG     (NH / NG)          // 56
#define INNER   (NH * HD)          // 7168
#define IN2     (2 * INNER)        // 14336

// ---------------- scratch (device globals; no cudaMalloc allowed) ----------
__device__ float g_xz[(size_t)L_TOK * IN2];            // [x | z]
__device__ float g_yg[(size_t)L_TOK * INNER];          // gated y (tf32-rounded)
__device__ float g_states[(size_t)NCHUNK * NH * HD * DS];   // [k][h][p][n]
__device__ float g_prev[(size_t)NCHUNK * NH * DS * HD];     // [k][h][n][p]
__device__ float g_hid[(size_t)L_TOK * DMODEL];        // tf32-rounded hidden
__device__ float g_w1[(size_t)IN2 * DMODEL];           // tf32-rounded W_in
__device__ float g_w2[(size_t)DMODEL * INNER];         // tf32-rounded W_out
__device__ float g_dt[NH];
__device__ float g_a[NH];

// ---------------- helpers ---------------------------------------------------
__device__ __forceinline__ uint32_t s2u(const void* p) {
    uint32_t a;
    asm("{ .reg .u64 t; cvta.to.shared.u64 t, %1; cvt.u32.u64 %0, t; }"
        : "=r"(a) : "l"(p));
    return a;
}
__device__ __forceinline__ void cpasync16(uint32_t saddr, const void* g) {
    asm volatile("cp.async.cg.shared.global [%0], [%1], 16;" :: "r"(saddr), "l"(g));
}
__device__ __forceinline__ float rtf32(float x) {
    uint32_t r;
    asm("cvt.rna.tf32.f32 %0, %1;" : "=r"(r) : "f"(x));
    return __uint_as_float(r);
}
__device__ __forceinline__ void ffma2(float2 &d, const float2 &a, const float2 &b) {
    unsigned long long ud, ua, ub;
    __builtin_memcpy(&ud, &d, 8);
    __builtin_memcpy(&ua, &a, 8);
    __builtin_memcpy(&ub, &b, 8);
    asm("fma.rn.f32x2 %0, %1, %2, %0;" : "+l"(ud) : "l"(ua), "l"(ub));
    __builtin_memcpy(&d, &ud, 8);
}
// ldmatrix x4: four 8x8 b16 matrices (= 8x4 b32 each); lane l of each matrix
// receives element (row = l>>2, col = l&3) as one b32 — exactly the tf32
// m16n8k8 fragment map.
__device__ __forceinline__ void ldsm4(uint32_t* r, uint32_t addr) {
    asm volatile("ldmatrix.sync.aligned.m8n8.x4.shared.b16 {%0,%1,%2,%3}, [%4];"
                 : "=r"(r[0]), "=r"(r[1]), "=r"(r[2]), "=r"(r[3]) : "r"(addr));
}
// m16n8k8 tf32 mma, uint32 operands
__device__ __forceinline__ void mma16n8k8(float* d, const uint32_t* a,
                                          uint32_t b0, uint32_t b1) {
    asm volatile(
        "mma.sync.aligned.m16n8k8.row.col.f32.tf32.tf32.f32 "
        "{%0,%1,%2,%3}, {%4,%5,%6,%7}, {%8,%9}, {%0,%1,%2,%3};"
        : "+f"(d[0]), "+f"(d[1]), "+f"(d[2]), "+f"(d[3])
        : "r"(a[0]), "r"(a[1]), "r"(a[2]), "r"(a[3]), "r"(b0), "r"(b1));
}

// ---------------- per-head parameters --------------------------------------
__global__ void hparams_kernel(const float* __restrict__ A_log,
                               const float* __restrict__ dt_bias) {
    int h = threadIdx.x;
    if (h < NH) {
        float xv = 0.1f + dt_bias[h];
        float sp = (xv > 20.f) ? xv : log1pf(expf(xv));
        g_dt[h] = sp;
        g_a[h]  = -expf(A_log[h]) * sp;
    }
}

// ---------------- round-to-nearest tf32 preprocessing ----------------------
__global__ void round_tf32_kernel(const float* __restrict__ in, float* __restrict__ out, int n4) {
    int i = blockIdx.x * blockDim.x + threadIdx.x;
    int stride = gridDim.x * blockDim.x;
    for (; i < n4; i += stride) {
        float4 v = ((const float4*)in)[i];
        v.x = rtf32(v.x); v.y = rtf32(v.y); v.z = rtf32(v.z); v.w = rtf32(v.w);
        ((float4*)out)[i] = v;
    }
}

// ---------------- mma.sync TF32 GEMM: C[M,N] = A[M,K]*B[N,K]^T -------------
// Block 128(M) x 256(N) x 32(K); 512 threads = 16 warps as 2(m) x 8(n);
// warp tile 64x32. ldmatrix fragment loads. 4-stage cp.async multistage.
#define KT       32
#define ALD      36
#define A_FLT    (128 * ALD)                 // 4608 floats / stage
#define B_FLT    (256 * ALD)                 // 9216 floats / stage
#define STG_FLT  (A_FLT + B_FLT)             // 13824 floats
#define STGB     (STG_FLT * 4)               // 55296 B
#define NSTG     4
#define GM_SMEM  (NSTG * STGB)               // 221184 B

__global__ __launch_bounds__(512, 1)
void gemm_mma(const float* __restrict__ A, const float* __restrict__ B,
              float* __restrict__ C, int M, int N, int K, int tiles_m) {
    extern __shared__ __align__(16) float sm[];
    uint32_t sbase = s2u(sm);

    int tid = threadIdx.x, lane = tid & 31, wid = tid >> 5;
    int wm = (wid & 1) * 64;          // warp m offset
    int wn = (wid >> 1) * 32;         // warp n offset
    int bid = blockIdx.x;
    int m0 = (bid % tiles_m) * 128;
    int n0 = (bid / tiles_m) * 256;

    // cp.async per-thread source/dest
    const float* gA[2]; uint32_t oA[2];
    #pragma unroll
    for (int it = 0; it < 2; it++) {
        int q = tid + it * 512;             // 1024 float4 over A tile
        int r = q >> 3, c4 = (q & 7) * 4;
        gA[it] = A + (size_t)(m0 + r) * K + c4;
        oA[it] = (uint32_t)(r * ALD + c4) * 4;
    }
    const float* gB[4]; uint32_t oB[4];
    #pragma unroll
    for (int it = 0; it < 4; it++) {
        int q = tid + it * 512;             // 2048 float4 over B tile
        int r = q >> 3, c4 = (q & 7) * 4;
        gB[it] = B + (size_t)(n0 + r) * K + c4;
        oB[it] = (uint32_t)(A_FLT + r * ALD + c4) * 4;
    }

    // ldmatrix per-lane addresses
    // A matrices: m0=(row+0,col+0) m1=(row+8,col+0) m2=(row+0,col+4) m3=(row+8,col+4)
    int lr = lane & 7;
    int a_row = lr + ((lane >> 3) & 1) * 8;
    int a_col = ((lane >> 4) & 1) * 4;
    uint32_t aoff[4];
    #pragma unroll
    for (int t = 0; t < 4; t++)
        aoff[t] = sbase + (uint32_t)(((wm + t * 16 + a_row) * ALD + a_col) * 4);
    // B matrices: m0=(n+0,c+0) m1=(n+0,c+4) m2=(n+8,c+0) m3=(n+8,c+4)
    int b_row = lr + ((lane >> 4) & 1) * 8;
    int b_col = ((lane >> 3) & 1) * 4;
    uint32_t boff[2];
    #pragma unroll
    for (int v = 0; v < 2; v++)
        boff[v] = sbase + (uint32_t)((A_FLT + (wn + v * 16 + b_row) * ALD + b_col) * 4);

    const int NKC = K / KT;

    // prologue: fill stages 0..NSTG-2
    #pragma unroll
    for (int s = 0; s < NSTG - 1; s++) {
        uint32_t sb = sbase + s * STGB;
        #pragma unroll
        for (int it = 0; it < 2; it++) cpasync16(sb + oA[it], gA[it] + s * KT);
        #pragma unroll
        for (int it = 0; it < 4; it++) cpasync16(sb + oB[it], gB[it] + s * KT);
        asm volatile("cp.async.commit_group;");
    }

    float acc[4][4][4];
    #pragma unroll
    for (int t = 0; t < 4; t++)
        #pragma unroll
        for (int u = 0; u < 4; u++)
            #pragma unroll
            for (int v = 0; v < 4; v++) acc[t][u][v] = 0.f;

    for (int kb = 0; kb < NKC; kb++) {
        int st = kb & (NSTG - 1);
        asm volatile("cp.async.wait_group %0;" :: "n"(NSTG - 2));
        __syncthreads();

        // refill the stage consumed at iter kb-1
        {
            int fc = kb + NSTG - 1;
            if (fc < NKC) {
                uint32_t sb = sbase + (fc & (NSTG - 1)) * STGB;
                #pragma unroll
                for (int it = 0; it < 2; it++) cpasync16(sb + oA[it], gA[it] + fc * KT);
                #pragma unroll
                for (int it = 0; it < 4; it++) cpasync16(sb + oB[it], gB[it] + fc * KT);
            }
            asm volatile("cp.async.commit_group;");
        }

        uint32_t stb = st * STGB;
        #pragma unroll
        for (int ks = 0; ks < 4; ks++) {
            uint32_t kadd = stb + ks * 32;   // ks*8 floats
            uint32_t af[4][4];
            #pragma unroll
            for (int t = 0; t < 4; t++) ldsm4(af[t], aoff[t] + kadd);
            uint32_t bf[2][4];
            #pragma unroll
            for (int v = 0; v < 2; v++) ldsm4(bf[v], boff[v] + kadd);
            #pragma unroll
            for (int u = 0; u < 4; u++) {
                uint32_t b0 = bf[u >> 1][(u & 1) * 2 + 0];
                uint32_t b1 = bf[u >> 1][(u & 1) * 2 + 1];
                #pragma unroll
                for (int t = 0; t < 4; t++) mma16n8k8(acc[t][u], af[t], b0, b1);
            }
        }
    }

    int g4 = lane >> 2, c4i = lane & 3;
    #pragma unroll
    for (int t = 0; t < 4; t++) {
        int r0 = m0 + wm + t * 16 + g4;
        #pragma unroll
        for (int u = 0; u < 4; u++) {
            int col = n0 + wn + u * 8 + c4i * 2;
            *(float2*)&C[(size_t)r0 * N + col] = make_float2(acc[t][u][0], acc[t][u][1]);
            *(float2*)&C[(size_t)(r0 + 8) * N + col] = make_float2(acc[t][u][2], acc[t][u][3]);
        }
    }
}

// ---------------- per-chunk end states: S[k,h,p,n] --------------------------
__global__ void states_kernel(const float* __restrict__ Bin) {
    int k = blockIdx.x, h = blockIdx.y;
    int tid = threadIdx.x;
    int p = tid & 63, quad = tid >> 6;
    float a = g_a[h], dtv = g_dt[h];
    int g = h / HPG;
    __shared__ float sx[8 * 64], sbuf[8 * 64];
    float acc[16];
    #pragma unroll
    for (int m = 0; m < 16; m++) acc[m] = 0.f;
    int lb = k * CHUNKSZ;
    for (int jb = 0; jb < CHUNKSZ; jb += 8) {
        __syncthreads();
        #pragma unroll
        for (int it = 0; it < 2; it++) {
            int e = tid + it * 256;
            int jj = e >> 6, pp = e & 63;
            int l = lb + jb + jj;
            sx[e] = g_xz[(size_t)l * IN2 + h * HD + pp];
            sbuf[e] = Bin[((size_t)l * NG + g) * DS + pp];
        }
        __syncthreads();
        #pragma unroll
        for (int jj = 0; jj < 8; jj++) {
            int j = jb + jj;
            float dec = expf(a * (float)(CHUNKSZ - 1 - j)) * dtv;
            float v = sx[jj * 64 + p] * dec;
            #pragma unroll
            for (int m = 0; m < 16; m++)
                acc[m] += v * sbuf[jj * 64 + quad + 4 * m];
        }
    }
    size_t base = ((size_t)(k * NH + h)) << 12;
    #pragma unroll
    for (int m = 0; m < 16; m++)
        g_states[base + p * 64 + quad + 4 * m] = acc[m];
}

// ---------------- inter-chunk scan -----------------------------------------
__global__ void scan_kernel() {
    int h = blockIdx.x;
    float cd = expf(g_a[h] * (float)CHUNKSZ);
    for (int e = threadIdx.x; e < HD * DS; e += 256) {
        int p = e >> 6, n = e & 63;
        float carry = 0.f;
        #pragma unroll
        for (int k = 0; k < NCHUNK; k++) {
            size_t base = ((size_t)(k * NH + h)) << 12;
            g_prev[base + n * 64 + p] = carry;
            carry = carry * cd + g_states[base + e];
        }
    }
}

// ---------------- intra-chunk + off-diagonal + gate (f32x2 packed) ----------
#define CLD 65
#define SY_FLOATS (256*64 + 256*64 + 64*64 + 256*CLD + 288)
__global__ __launch_bounds__(256, 1)
void yblock_kernel(const float* __restrict__ Bin, const float* __restrict__ Cin,
                   const float* __restrict__ Dv) {
    extern __shared__ float sm[];
    float* sX   = sm;
    float* sB   = sX + 256 * 64;
    float* sP   = sB + 256 * 64;
    float* sC   = sP + 64 * 64;
    float* sDec = sC + 256 * CLD;

    int k = blockIdx.x, h = blockIdx.y;
    int tid = threadIdx.x;
    float a = g_a[h], dtv = g_dt[h], Dh = Dv[h];
    int g = h / HPG;
    int lb = k * CHUNKSZ;

    float4* sX4 = (float4*)sX;
    float4* sB4 = (float4*)sB;
    float4* sP4 = (float4*)sP;
    #pragma unroll
    for (int it = 0; it < 16; it++) {
        int q = tid + it * 256;
        int j = q >> 4, p4 = q & 15;
        sX4[q] = *(const float4*)&g_xz[(size_t)(lb + j) * IN2 + h * HD + p4 * 4];
        sB4[q] = *(const float4*)&Bin[((size_t)(lb + j) * NG + g) * DS + p4 * 4];
    }
    {
        size_t pbase = ((size_t)(k * NH + h)) << 12;
        #pragma unroll
        for (int it = 0; it < 4; it++) {
            int q = tid + it * 256;
            sP4[q] = *(const float4*)&g_prev[pbase + (size_t)q * 4];
        }
    }
    for (int d = tid; d < CHUNKSZ + 1; d += 256) sDec[d] = expf(a * (float)d);

    float2 cre2[32];
    {
        const float4* Crow = (const float4*)&Cin[((size_t)(lb + tid) * NG + g) * DS];
        #pragma unroll
        for (int n4 = 0; n4 < 16; n4++) {
            float4 v = Crow[n4];
            cre2[2 * n4 + 0] = make_float2(v.x, v.y);
            cre2[2 * n4 + 1] = make_float2(v.z, v.w);
            sC[tid * CLD + 4 * n4 + 0] = v.x;
            sC[tid * CLD + 4 * n4 + 1] = v.y;
            sC[tid * CLD + 4 * n4 + 2] = v.z;
            sC[tid * CLD + 4 * n4 + 3] = v.w;
        }
    }
    __syncthreads();

    int i = tid;
    float2 acc2[32];
    #pragma unroll
    for (int p = 0; p < 32; p++) acc2[p] = make_float2(0.f, 0.f);

    for (int j = 0; j <= i; j++) {
        const float4* bj = (const float4*)&sB[j * 64];
        float2 s2 = make_float2(0.f, 0.f);
        #pragma unroll
        for (int m4 = 0; m4 < 16; m4++) {
            float4 bv = bj[m4];
            ffma2(s2, cre2[2 * m4 + 0], make_float2(bv.x, bv.y));
            ffma2(s2, cre2[2 * m4 + 1], make_float2(bv.z, bv.w));
        }
        float w = (s2.x + s2.y) * sDec[i - j] * dtv;
        float2 w2 = make_float2(w, w);
        const float4* xj = (const float4*)&sX[j * 64];
        #pragma unroll
        for (int p4 = 0; p4 < 16; p4++) {
            float4 xv = xj[p4];
            ffma2(acc2[2 * p4 + 0], w2, make_float2(xv.x, xv.y));
            ffma2(acc2[2 * p4 + 1], w2, make_float2(xv.z, xv.w));
        }
    }
    {
        float coef = sDec[i + 1];
        for (int n = 0; n < 64; n++) {
            float w = sC[i * CLD + n] * coef;
            float2 w2 = make_float2(w, w);
            const float4* pn = (const float4*)&sP[n * 64];
            #pragma unroll
            for (int p4 = 0; p4 < 16; p4++) {
                float4 pv = pn[p4];
                ffma2(acc2[2 * p4 + 0], w2, make_float2(pv.x, pv.y));
                ffma2(acc2[2 * p4 + 1], w2, make_float2(pv.z, pv.w));
            }
        }
    }
    {
        int l = lb + i;
        const float* zrow = &g_xz[(size_t)l * IN2 + INNER + h * HD];
        const float* xrow = &sX[i * 64];
        float* outp = &g_yg[(size_t)l * INNER + h * HD];
        #pragma unroll
        for (int p4 = 0; p4 < 16; p4++) {
            float4 zv = *(const float4*)&zrow[p4 * 4];
            float4 xv = *(const float4*)&xrow[p4 * 4];
            float4 o;
            o.x = rtf32((acc2[2 * p4 + 0].x + xv.x * Dh) / (1.f + expf(-zv.x)));
            o.y = rtf32((acc2[2 * p4 + 0].y + xv.y * Dh) / (1.f + expf(-zv.y)));
            o.z = rtf32((acc2[2 * p4 + 1].x + xv.z * Dh) / (1.f + expf(-zv.z)));
            o.w = rtf32((acc2[2 * p4 + 1].y + xv.w * Dh) / (1.f + expf(-zv.w)));
            *(float4*)&outp[p4 * 4] = o;
        }
    }
}

// ---------------- launcher --------------------------------------------------
extern "C" void kernel_launch(void* const* d_in, const int* in_sizes, int n_in,
                              void* d_out, int out_size) {
    (void)in_sizes; (void)n_in; (void)out_size;
    const float* hidden = (const float*)d_in[0];
    const float* W_in   = (const float*)d_in[1];
    const float* W_out  = (const float*)d_in[2];
    const float* A_log  = (const float*)d_in[3];
    const float* Dv     = (const float*)d_in[4];
    const float* dtb    = (const float*)d_in[5];
    const float* Bin    = (const float*)d_in[6];
    const float* Cin    = (const float*)d_in[7];
    float* out = (float*)d_out;

    float *xz_ptr, *yg_ptr, *hid_ptr, *w1_ptr, *w2_ptr;
    cudaGetSymbolAddress((void**)&xz_ptr, g_xz);
    cudaGetSymbolAddress((void**)&yg_ptr, g_yg);
    cudaGetSymbolAddress((void**)&hid_ptr, g_hid);
    cudaGetSymbolAddress((void**)&w1_ptr, g_w1);
    cudaGetSymbolAddress((void**)&w2_ptr, g_w2);

    cudaFuncSetAttribute(gemm_mma, cudaFuncAttributeMaxDynamicSharedMemorySize, GM_SMEM);

    // launch order chosen so gemm1 is the 4th launch (ncu captures it)
    hparams_kernel<<<1, 128>>>(A_log, dtb);                                   // 1
    round_tf32_kernel<<<1184, 256>>>(W_in,   w1_ptr,  (IN2 * DMODEL) / 4);    // 2
    round_tf32_kernel<<<1184, 256>>>(hidden, hid_ptr, (L_TOK * DMODEL) / 4);  // 3

    // GEMM1: xz[L, IN2] = hid[L, DMODEL] @ W_in[IN2, DMODEL]^T
    {
        int tiles_m = L_TOK / 128;      // 32
        int tiles_n = IN2 / 256;        // 56
        gemm_mma<<<tiles_m * tiles_n, 512, GM_SMEM>>>(hid_ptr, w1_ptr, xz_ptr,
                                                      L_TOK, IN2, DMODEL, tiles_m);  // 4
    }

    states_kernel<<<dim3(NCHUNK, NH), 256>>>(Bin);                            // 5
    scan_kernel<<<NH, 256>>>();                                               // 6

    {
        size_t smem = (size_t)SY_FLOATS * sizeof(float);
        cudaFuncSetAttribute(yblock_kernel,
                             cudaFuncAttributeMaxDynamicSharedMemorySize, (int)smem);
        yblock_kernel<<<dim3(NCHUNK, NH), 256, smem>>>(Bin, Cin, Dv);         // 7
    }

    round_tf32_kernel<<<1184, 256>>>(W_out, w2_ptr, (DMODEL * INNER) / 4);    // 8

    // GEMM2: out[L, DMODEL] = yg[L, INNER] @ W_out[DMODEL, INNER]^T
    {
        int tiles_m = L_TOK / 128;      // 32
        int tiles_n = DMODEL / 256;     // 14
        gemm_mma<<<tiles_m * tiles_n, 512, GM_SMEM>>>(yg_ptr, w2_ptr, out,
                                                      L_TOK, DMODEL, INNER, tiles_m); // 9
    }
}